// round 16
// baseline (speedup 1.0000x reference)
#include <cuda_runtime.h>
#include <cuda_bf16.h>
#include <math.h>
#include <stdint.h>

#define DD 256
#define LL 128
#define NEG_SLOPE 0.2f
#define LN_EPS 1e-5f
#define ASTR 264            // A smem row stride in bf16 halves

// K1 smem: A hi/lo + misc floats
#define A_HI 0                               // [64][264] bf16 = 33792 B
#define A_LO 33792
#define MISC 67584                           // floats
// misc floats: qb 256, w 256, s_part 256(4*64), p 64, red 32 = 864
static const int K1_SMEM = MISC + 864 * 4;   // 71040

// W2 in MMA-fragment-major layout (exact ldmatrix register image):
// [plane 2 (hi/lo)][ks 16][ng 16][lane 32][16B]  = 256 KB
__device__ __align__(16) __nv_bfloat16 g_Wf[131072];
__device__ __align__(16) float g_W1T[256 * 256];        // W1 transposed [k][d]
__device__ __align__(16) float g_W2T[256 * 256];        // W2 transposed [k][d]
__device__ __align__(16) float g_qb[2048L * 256];       // qb = mol@W1^T + b1 + b2
__device__ __align__(16) float g_y [2048L * 2 * 256];   // per-half unnormalized y
__device__ __align__(16) float g_st[2048L * 2 * 4];     // per-half (m, Z, sumattn)

// Fragment table: for unit (plane, ks, ng), lane t holds the ldmatrix image
__global__ void prep_wf(const float* __restrict__ W2) {
    const int idx  = blockIdx.x * 256 + threadIdx.x;   // 0..16383
    const int lane = idx & 31;
    const int unit = idx >> 5;
    const int ng    = unit & 15;
    const int ks    = (unit >> 4) & 15;
    const int plane = unit >> 8;
    const int n0 = ng * 16, k0 = ks * 16;
    const int r = lane >> 2, m = lane & 3;
    __nv_bfloat16 vals[8];
    int c = 0;
    #pragma unroll
    for (int rr = 0; rr < 2; ++rr)
        #pragma unroll
        for (int kk = 0; kk < 2; ++kk)
            #pragma unroll
            for (int e = 0; e < 2; ++e) {
                const float v = W2[(long)(n0 + 8 * rr + r) * DD + k0 + 8 * kk + 2 * m + e];
                const __nv_bfloat16 h = __float2bfloat16(v);
                vals[c++] = (plane == 0) ? h
                          : __float2bfloat16(v - __bfloat162float(h));
            }
    *(uint4*)((char*)g_Wf + (long)idx * 16) = *(uint4*)vals;
}

// transpose W1 and W2 (blockIdx.x = k, threadIdx.x = d; writes coalesced)
__global__ void prep_wt(const float* __restrict__ W1, const float* __restrict__ W2) {
    const int k = blockIdx.x, d = threadIdx.x;
    g_W1T[(long)k * 256 + d] = W1[(long)d * 256 + k];
    g_W2T[(long)k * 256 + d] = W2[(long)d * 256 + k];
}

// qb GEMV: 8 molecules per CTA, coalesced W1T reads
__global__ __launch_bounds__(256)
void prep_qb(const float* __restrict__ mol,
             const float* __restrict__ b1, const float* __restrict__ b2) {
    __shared__ __align__(16) float mol_il[256 * 8];   // [k][m]
    const int bm0 = blockIdx.x * 8;
    const int tid = threadIdx.x;
    for (int i = tid; i < 8 * 256; i += 256) {
        const int k = i >> 3, m = i & 7;
        mol_il[i] = mol[(long)(bm0 + m) * 256 + k];
    }
    __syncthreads();
    const int d = tid;
    const float bb = b1[d] + b2[d];
    float acc[8];
    #pragma unroll
    for (int m = 0; m < 8; ++m) acc[m] = bb;
    #pragma unroll 4
    for (int k = 0; k < 256; ++k) {
        const float wv = g_W1T[(long)k * 256 + d];   // coalesced
        const float4 y0 = *(const float4*)(mol_il + k * 8);
        const float4 y1 = *(const float4*)(mol_il + k * 8 + 4);
        acc[0] += y0.x * wv; acc[1] += y0.y * wv;
        acc[2] += y0.z * wv; acc[3] += y0.w * wv;
        acc[4] += y1.x * wv; acc[5] += y1.y * wv;
        acc[6] += y1.z * wv; acc[7] += y1.w * wv;
    }
    #pragma unroll
    for (int m = 0; m < 8; ++m) g_qb[(long)(bm0 + m) * 256 + d] = acc[m];
}

static __device__ __forceinline__ uint32_t smem_u32(const void* p) {
    uint32_t a;
    asm("{ .reg .u64 t; cvta.to.shared.u64 t, %1; cvt.u32.u64 %0, t; }"
        : "=r"(a) : "l"(p));
    return a;
}

#define LDSM_X4(r0, r1, r2, r3, addr) \
    asm volatile("ldmatrix.sync.aligned.m8n8.x4.shared.b16 {%0,%1,%2,%3}, [%4];" \
        : "=r"(r0), "=r"(r1), "=r"(r2), "=r"(r3) : "r"(addr))
#define MMA_BF16(c, a, b0, b1) \
    asm volatile("mma.sync.aligned.m16n8k16.row.col.f32.bf16.bf16.f32 " \
        "{%0,%1,%2,%3}, {%4,%5,%6,%7}, {%8,%9}, {%0,%1,%2,%3};" \
        : "+f"((c)[0]), "+f"((c)[1]), "+f"((c)[2]), "+f"((c)[3]) \
        : "r"((a)[0]), "r"((a)[1]), "r"((a)[2]), "r"((a)[3]), "r"(b0), "r"(b1))

// K1: per-CTA = 64 atoms of one molecule half. Barrier-free MMA mainloop.
// (identical to round-14 kernel — known good)
__global__ __launch_bounds__(256, 2)
void k1_scores(const float* __restrict__ atom,    // [B,L,D]
               const float* __restrict__ attend,  // [B,L,1]
               const float* __restrict__ smask,   // [B,L,1]
               const float* __restrict__ w_align, // [D,1]
               const float* __restrict__ b_align) // [1]
{
    extern __shared__ char smem[];
    const uint32_t smb = smem_u32(smem);
    float* qb_s   = (float*)(smem + MISC);
    float* w_s    = qb_s + 256;
    float* s_part = w_s + 256;    // [4][64]
    float* p_arr  = s_part + 256; // 64
    float* red    = p_arr + 64;   // 32

    const int bx   = blockIdx.x;
    const int b    = bx >> 1;
    const int h    = bx & 1;
    const int tid  = threadIdx.x;
    const int lane = tid & 31;
    const int wid  = tid >> 5;
    const int mq   = wid >> 2;
    const int nq   = wid & 3;

    qb_s[tid] = g_qb[(long)b * 256 + tid];
    w_s[tid]  = w_align[tid];
    const float bal = b_align[0];

    const long abase = ((long)b * LL + 64 * h) * DD;
    for (int idx = tid; idx < 64 * (DD / 2); idx += 256) {
        const int r  = idx >> 7;
        const int kp = idx & 127;
        const float2 v = ((const float2*)(atom + abase + (long)r * DD))[kp];
        __nv_bfloat16 hx = __float2bfloat16(v.x);
        __nv_bfloat16 hy = __float2bfloat16(v.y);
        __nv_bfloat16 lx = __float2bfloat16(v.x - __bfloat162float(hx));
        __nv_bfloat16 ly = __float2bfloat16(v.y - __bfloat162float(hy));
        const int off = (r * ASTR + kp * 2) * 2;
        __nv_bfloat162 hv; hv.x = hx; hv.y = hy;
        __nv_bfloat162 lv; lv.x = lx; lv.y = ly;
        *(__nv_bfloat162*)(smem + A_HI + off) = hv;
        *(__nv_bfloat162*)(smem + A_LO + off) = lv;
    }

    uint32_t addrAh[2], addrAl[2];
    {
        const uint32_t aColh = (lane >> 4) << 3;
        #pragma unroll
        for (int mt = 0; mt < 2; ++mt) {
            const uint32_t off = (((uint32_t)(32 * mq + 16 * mt) + (lane & 15)) * ASTR + aColh) * 2;
            addrAh[mt] = smb + A_HI + off;
            addrAl[mt] = smb + A_LO + off;
        }
    }
    const char* bB0 = (const char*)g_Wf + ((uint32_t)(nq * 2 + 0)) * 512 + (uint32_t)lane * 16;
    const char* bB1 = (const char*)g_Wf + ((uint32_t)(nq * 2 + 1)) * 512 + (uint32_t)lane * 16;

    __syncthreads();

    float sc[2][2] = {{0.f, 0.f}, {0.f, 0.f}};

    #pragma unroll 1
    for (int np = 0; np < 2; ++np) {
        float acc[2][4][4];
        #pragma unroll
        for (int mt = 0; mt < 2; ++mt)
            #pragma unroll
            for (int j = 0; j < 4; ++j)
                #pragma unroll
                for (int q = 0; q < 4; ++q) acc[mt][j][q] = 0.f;

        const char* b0 = bB0 + np * 4096;
        const char* b1 = bB1 + np * 4096;

        uint4 cBh0 = *(const uint4*)(b0);
        uint4 cBh1 = *(const uint4*)(b1);
        uint4 cBl0 = *(const uint4*)(b0 + 131072);
        uint4 cBl1 = *(const uint4*)(b1 + 131072);

        #pragma unroll
        for (int ks = 0; ks < 16; ++ks) {
            uint4 nBh0, nBh1, nBl0, nBl1;
            if (ks < 15) {
                const int o = (ks + 1) * 8192;
                nBh0 = *(const uint4*)(b0 + o);
                nBh1 = *(const uint4*)(b1 + o);
                nBl0 = *(const uint4*)(b0 + 131072 + o);
                nBl1 = *(const uint4*)(b1 + 131072 + o);
            }
            uint32_t fAh[2][4], fAl[2][4];
            const uint32_t koA = (uint32_t)ks * 32;
            LDSM_X4(fAh[0][0], fAh[0][1], fAh[0][2], fAh[0][3], addrAh[0] + koA);
            LDSM_X4(fAh[1][0], fAh[1][1], fAh[1][2], fAh[1][3], addrAh[1] + koA);
            LDSM_X4(fAl[0][0], fAl[0][1], fAl[0][2], fAl[0][3], addrAl[0] + koA);
            LDSM_X4(fAl[1][0], fAl[1][1], fAl[1][2], fAl[1][3], addrAl[1] + koA);

            #pragma unroll
            for (int mt = 0; mt < 2; ++mt) {
                float* A0 = acc[mt][0];
                float* A1 = acc[mt][1];
                float* A2 = acc[mt][2];
                float* A3 = acc[mt][3];
                MMA_BF16(A0, fAh[mt], cBh0.x, cBh0.y);
                MMA_BF16(A0, fAl[mt], cBh0.x, cBh0.y);
                MMA_BF16(A0, fAh[mt], cBl0.x, cBl0.y);
                MMA_BF16(A1, fAh[mt], cBh0.z, cBh0.w);
                MMA_BF16(A1, fAl[mt], cBh0.z, cBh0.w);
                MMA_BF16(A1, fAh[mt], cBl0.z, cBl0.w);
                MMA_BF16(A2, fAh[mt], cBh1.x, cBh1.y);
                MMA_BF16(A2, fAl[mt], cBh1.x, cBh1.y);
                MMA_BF16(A2, fAh[mt], cBl1.x, cBl1.y);
                MMA_BF16(A3, fAh[mt], cBh1.z, cBh1.w);
                MMA_BF16(A3, fAl[mt], cBh1.z, cBh1.w);
                MMA_BF16(A3, fAh[mt], cBl1.z, cBl1.w);
            }
            cBh0 = nBh0; cBh1 = nBh1; cBl0 = nBl0; cBl1 = nBl1;
        }

        #pragma unroll
        for (int mt = 0; mt < 2; ++mt)
            #pragma unroll
            for (int j = 0; j < 4; ++j) {
                const int c = np * 128 + nq * 32 + (j >> 1) * 16 + (j & 1) * 8 + (lane & 3) * 2;
                const float q0 = qb_s[c], q1 = qb_s[c + 1];
                const float w0 = w_s[c],  w1 = w_s[c + 1];
                float v;
                v = q0 + acc[mt][j][0]; v = (v >= 0.f) ? v : NEG_SLOPE * v; sc[mt][0] += v * w0;
                v = q1 + acc[mt][j][1]; v = (v >= 0.f) ? v : NEG_SLOPE * v; sc[mt][0] += v * w1;
                v = q0 + acc[mt][j][2]; v = (v >= 0.f) ? v : NEG_SLOPE * v; sc[mt][1] += v * w0;
                v = q1 + acc[mt][j][3]; v = (v >= 0.f) ? v : NEG_SLOPE * v; sc[mt][1] += v * w1;
            }
    }

    #pragma unroll
    for (int mt = 0; mt < 2; ++mt)
        #pragma unroll
        for (int rh = 0; rh < 2; ++rh) {
            float t = sc[mt][rh];
            t += __shfl_xor_sync(0xffffffffu, t, 1);
            t += __shfl_xor_sync(0xffffffffu, t, 2);
            if ((lane & 3) == 0)
                s_part[nq * 64 + 32 * mq + 16 * mt + (lane >> 2) + 8 * rh] = t;
        }
    __syncthreads();

    // half-softmax stats over 64 atoms
    {
        float v = (tid < 64)
                ? (bal + (s_part[tid] + s_part[64 + tid])
                       + (s_part[128 + tid] + s_part[192 + tid])
                       + smask[(long)b * LL + 64 * h + tid])
                : -INFINITY;
        float t = v;
        #pragma unroll
        for (int off = 16; off; off >>= 1)
            t = fmaxf(t, __shfl_xor_sync(0xffffffffu, t, off));
        if (lane == 0) red[wid] = t;
        __syncthreads();
        float mx = red[0];
        #pragma unroll
        for (int w = 1; w < 8; ++w) mx = fmaxf(mx, red[w]);
        __syncthreads();

        float e = (tid < 64) ? __expf(v - mx) : 0.f;
        float att = (tid < 64) ? attend[(long)b * LL + 64 * h + tid] : 0.f;
        float pf = e * att;
        if (tid < 64) p_arr[tid] = pf;

        float ts = e;
        #pragma unroll
        for (int off = 16; off; off >>= 1)
            ts += __shfl_xor_sync(0xffffffffu, ts, off);
        if (lane == 0) red[8 + wid] = ts;
        float ta = pf;
        #pragma unroll
        for (int off = 16; off; off >>= 1)
            ta += __shfl_xor_sync(0xffffffffu, ta, off);
        if (lane == 0) red[16 + wid] = ta;
        __syncthreads();
        if (tid == 0) {
            float Z = 0.f, sa = 0.f;
            for (int w = 0; w < 8; ++w) { Z += red[8 + w]; sa += red[16 + w]; }
            float* st = g_st + (long)(b * 2 + h) * 4;
            st[0] = mx; st[1] = Z; st[2] = sa;
        }
    }
    __syncthreads();

    // y_half[k] = sum_a pf[a] * atom[a,k]
    {
        const float* Ab = atom + abase;
        float acc0 = 0.f, acc1 = 0.f;
        #pragma unroll 2
        for (int a = 0; a < 64; a += 2) {
            const float p0 = p_arr[a], p1 = p_arr[a + 1];
            if (p0 != 0.f) acc0 += p0 * Ab[(long)a * DD + tid];
            if (p1 != 0.f) acc1 += p1 * Ab[(long)(a + 1) * DD + tid];
        }
        g_y[((long)(b * 2 + h)) * 256 + tid] = acc0 + acc1;
    }
}

// K2: flash-combine + ctx GEMV (coalesced W2T) + LayerNorm. 8 mol/CTA.
__global__ __launch_bounds__(256)
void k2_tail(const float* __restrict__ b2,
             const float* __restrict__ gamma_, const float* __restrict__ beta_,
             float* __restrict__ out)
{
    __shared__ __align__(16) float y_il[256 * 8];   // [k][m]
    __shared__ __align__(16) float ctx_s[8 * 256];
    __shared__ float cs[8][4];
    const int bm0 = blockIdx.x * 8;
    const int tid = threadIdx.x;
    const int lane = tid & 31;
    const int wid = tid >> 5;

    if (tid < 8) {
        const float* st = g_st + (long)(bm0 + tid) * 8;
        const float m0 = st[0], Z0 = st[1], sa0 = st[2];
        const float m1 = st[4], Z1 = st[5], sa1 = st[6];
        const float mx = fmaxf(m0, m1);
        const float s0 = __expf(m0 - mx), s1 = __expf(m1 - mx);
        const float Z = Z0 * s0 + Z1 * s1;
        const float c0 = s0 / Z, c1 = s1 / Z;
        cs[tid][0] = c0; cs[tid][1] = c1;
        cs[tid][2] = sa0 * c0 + sa1 * c1;   // sum of attn
    }
    __syncthreads();
    for (int i = tid; i < 8 * 256; i += 256) {
        const int k = i >> 3, m = i & 7;
        y_il[i] = g_y[(long)(bm0 + m) * 2 * 256 + k] * cs[m][0]
                + g_y[((long)(bm0 + m) * 2 + 1) * 256 + k] * cs[m][1];
    }
    __syncthreads();
    {
        const int d = tid;
        const float b2d = b2[d];
        float acc[8];
        #pragma unroll
        for (int m = 0; m < 8; ++m) acc[m] = cs[m][2] * b2d;
        #pragma unroll 4
        for (int k = 0; k < 256; ++k) {
            const float wv = g_W2T[(long)k * 256 + d];   // coalesced
            const float4 y0 = *(const float4*)(y_il + k * 8);
            const float4 y1 = *(const float4*)(y_il + k * 8 + 4);
            acc[0] += y0.x * wv; acc[1] += y0.y * wv;
            acc[2] += y0.z * wv; acc[3] += y0.w * wv;
            acc[4] += y1.x * wv; acc[5] += y1.y * wv;
            acc[6] += y1.z * wv; acc[7] += y1.w * wv;
        }
        #pragma unroll
        for (int m = 0; m < 8; ++m) ctx_s[m * 256 + d] = acc[m];
    }
    __syncthreads();
    {   // LN: warp w -> molecule w
        const int m = wid;
        float vals[8];
        float s1 = 0.f;
        #pragma unroll
        for (int j = 0; j < 8; ++j) {
            vals[j] = ctx_s[m * 256 + lane + 32 * j];
            s1 += vals[j];
        }
        #pragma unroll
        for (int off = 16; off; off >>= 1)
            s1 += __shfl_xor_sync(0xffffffffu, s1, off);
        const float mu = s1 * (1.f / 256.f);
        float s2 = 0.f;
        #pragma unroll
        for (int j = 0; j < 8; ++j) {
            const float d = vals[j] - mu;
            s2 += d * d;
        }
        #pragma unroll
        for (int off = 16; off; off >>= 1)
            s2 += __shfl_xor_sync(0xffffffffu, s2, off);
        const float inv = rsqrtf(s2 * (1.f / 256.f) + LN_EPS);
        #pragma unroll
        for (int j = 0; j < 8; ++j) {
            const int d = lane + 32 * j;
            out[(long)(bm0 + m) * 256 + d] =
                (vals[j] - mu) * inv * gamma_[d] + beta_[d];
        }
    }
}

extern "C" void kernel_launch(void* const* d_in, const int* in_sizes, int n_in,
                              void* d_out, int out_size)
{
    const float* mol     = (const float*)d_in[0];
    const float* atom    = (const float*)d_in[1];
    const float* attend  = (const float*)d_in[2];
    const float* smask   = (const float*)d_in[3];
    const float* W1      = (const float*)d_in[4];
    const float* b1      = (const float*)d_in[5];
    const float* W2      = (const float*)d_in[6];
    const float* b2      = (const float*)d_in[7];
    const float* w_align = (const float*)d_in[8];
    const float* b_align = (const float*)d_in[9];
    const float* gamma_  = (const float*)d_in[10];
    const float* beta_   = (const float*)d_in[11];
    float* out = (float*)d_out;

    const int B = in_sizes[0] / DD;

    prep_wf<<<64, 256>>>(W2);
    prep_wt<<<256, 256>>>(W1, W2);
    prep_qb<<<B / 8, 256>>>(mol, b1, b2);

    cudaFuncSetAttribute(k1_scores,
                         cudaFuncAttributeMaxDynamicSharedMemorySize, K1_SMEM);
    k1_scores<<<B * 2, 256, K1_SMEM>>>(atom, attend, smask, w_align, b_align);

    k2_tail<<<B / 8, 256>>>(b2, gamma_, beta_, out);
}

// round 17
// speedup vs baseline: 1.4297x; 1.4297x over previous
#include <cuda_runtime.h>
#include <cuda_bf16.h>
#include <math.h>
#include <stdint.h>

#define DD 256
#define LL 128
#define NEG_SLOPE 0.2f
#define LN_EPS 1e-5f
#define ASTR 264            // A smem row stride in bf16 halves

// K1 smem: A hi/lo + misc floats
#define A_HI 0                               // [64][264] bf16 = 33792 B
#define A_LO 33792
#define MISC 67584
// misc floats: qb 256, w 256, s_part 256(4*64), p 64, red 32, act 64(int) = 928
static const int K1_SMEM = MISC + 928 * 4;   // 71296

// W2 in MMA-fragment-major layout (exact ldmatrix register image):
// [plane 2 (hi/lo)][ks 16][ng 16][lane 32][16B]  = 256 KB
__device__ __align__(16) __nv_bfloat16 g_Wf[131072];
__device__ __align__(16) float g_W1T[256 * 256];        // W1 transposed [k][d]
__device__ __align__(16) float g_W2T[256 * 256];        // W2 transposed [k][d]
__device__ __align__(16) float g_qb[2048L * 256];       // qb = mol@W1^T + b1 + b2
__device__ __align__(16) float g_y [2048L * 2 * 256];   // per-half unnormalized y
__device__ __align__(16) float g_st[2048L * 2 * 4];     // per-half (m, Z)
__device__ int g_act[2048 * 128];                       // compacted active indices
__device__ int g_nact[2048];

// Fragment table: for unit (plane, ks, ng), lane t holds the ldmatrix image
__global__ void prep_wf(const float* __restrict__ W2) {
    const int idx  = blockIdx.x * 256 + threadIdx.x;   // 0..16383
    const int lane = idx & 31;
    const int unit = idx >> 5;
    const int ng    = unit & 15;
    const int ks    = (unit >> 4) & 15;
    const int plane = unit >> 8;
    const int n0 = ng * 16, k0 = ks * 16;
    const int r = lane >> 2, m = lane & 3;
    __nv_bfloat16 vals[8];
    int c = 0;
    #pragma unroll
    for (int rr = 0; rr < 2; ++rr)
        #pragma unroll
        for (int kk = 0; kk < 2; ++kk)
            #pragma unroll
            for (int e = 0; e < 2; ++e) {
                const float v = W2[(long)(n0 + 8 * rr + r) * DD + k0 + 8 * kk + 2 * m + e];
                const __nv_bfloat16 h = __float2bfloat16(v);
                vals[c++] = (plane == 0) ? h
                          : __float2bfloat16(v - __bfloat162float(h));
            }
    *(uint4*)((char*)g_Wf + (long)idx * 16) = *(uint4*)vals;
}

// transpose W1/W2 (blockIdx.x = k, threadIdx.x = d; writes coalesced)
__global__ void prep_wt(const float* __restrict__ W1, const float* __restrict__ W2) {
    const int k = blockIdx.x, d = threadIdx.x;
    g_W1T[(long)k * 256 + d] = W1[(long)d * 256 + k];
    g_W2T[(long)k * 256 + d] = W2[(long)d * 256 + k];
}

__global__ void prep_act(const float* __restrict__ attend) {
    const int b = blockIdx.x;
    const int tid = threadIdx.x, lane = tid & 31, w = tid >> 5;
    __shared__ int cnts[4];
    const int flag = (attend[(long)b * LL + tid] > 0.5f) ? 1 : 0;
    const unsigned bm = __ballot_sync(0xffffffffu, flag);
    if (lane == 0) cnts[w] = __popc(bm);
    __syncthreads();
    int base = 0;
    for (int i = 0; i < w; ++i) base += cnts[i];
    if (flag) g_act[b * LL + base + __popc(bm & ((1u << lane) - 1u))] = tid;
    if (tid == 0) g_nact[b] = cnts[0] + cnts[1] + cnts[2] + cnts[3];
}

// qb GEMV: 8 molecules per CTA, coalesced W1T reads
__global__ __launch_bounds__(256)
void prep_qb(const float* __restrict__ mol,
             const float* __restrict__ b1, const float* __restrict__ b2) {
    __shared__ __align__(16) float mol_il[256 * 8];   // [k][m]
    const int bm0 = blockIdx.x * 8;
    const int tid = threadIdx.x;
    for (int i = tid; i < 8 * 256; i += 256) {
        const int k = i >> 3, m = i & 7;
        mol_il[i] = mol[(long)(bm0 + m) * 256 + k];
    }
    __syncthreads();
    const int d = tid;
    const float bb = b1[d] + b2[d];
    float acc[8];
    #pragma unroll
    for (int m = 0; m < 8; ++m) acc[m] = bb;
    #pragma unroll 4
    for (int k = 0; k < 256; ++k) {
        const float wv = g_W1T[(long)k * 256 + d];   // coalesced
        const float4 y0 = *(const float4*)(mol_il + k * 8);
        const float4 y1 = *(const float4*)(mol_il + k * 8 + 4);
        acc[0] += y0.x * wv; acc[1] += y0.y * wv;
        acc[2] += y0.z * wv; acc[3] += y0.w * wv;
        acc[4] += y1.x * wv; acc[5] += y1.y * wv;
        acc[6] += y1.z * wv; acc[7] += y1.w * wv;
    }
    #pragma unroll
    for (int m = 0; m < 8; ++m) g_qb[(long)(bm0 + m) * 256 + d] = acc[m];
}

static __device__ __forceinline__ uint32_t smem_u32(const void* p) {
    uint32_t a;
    asm("{ .reg .u64 t; cvta.to.shared.u64 t, %1; cvt.u32.u64 %0, t; }"
        : "=r"(a) : "l"(p));
    return a;
}

#define LDSM_X4(r0, r1, r2, r3, addr) \
    asm volatile("ldmatrix.sync.aligned.m8n8.x4.shared.b16 {%0,%1,%2,%3}, [%4];" \
        : "=r"(r0), "=r"(r1), "=r"(r2), "=r"(r3) : "r"(addr))
#define MMA_BF16(c, a, b0, b1) \
    asm volatile("mma.sync.aligned.m16n8k16.row.col.f32.bf16.bf16.f32 " \
        "{%0,%1,%2,%3}, {%4,%5,%6,%7}, {%8,%9}, {%0,%1,%2,%3};" \
        : "+f"((c)[0]), "+f"((c)[1]), "+f"((c)[2]), "+f"((c)[3]) \
        : "r"((a)[0]), "r"((a)[1]), "r"((a)[2]), "r"((a)[3]), "r"(b0), "r"(b1))

// K1: CTA = up to 64 ACTIVE (compacted) atoms of one molecule half.
__global__ __launch_bounds__(256, 2)
void k1_scores(const float* __restrict__ atom,    // [B,L,D]
               const float* __restrict__ w_align, // [D,1]
               const float* __restrict__ b_align) // [1]
{
    extern __shared__ char smem[];
    const uint32_t smb = smem_u32(smem);
    float* qb_s   = (float*)(smem + MISC);
    float* w_s    = qb_s + 256;
    float* s_part = w_s + 256;    // [4][64]
    float* p_arr  = s_part + 256; // 64
    float* red    = p_arr + 64;   // 32
    int*   act_s  = (int*)(red + 32);   // 64

    const int bx   = blockIdx.x;
    const int b    = bx >> 1;
    const int h    = bx & 1;
    const int tid  = threadIdx.x;
    const int lane = tid & 31;
    const int wid  = tid >> 5;
    const int mq   = wid >> 2;
    const int nq   = wid & 3;

    const int nact = g_nact[b];
    const int base = 64 * h;
    if (base >= nact) {        // empty half: publish neutral stats, done
        if (tid == 0) {
            float* st = g_st + (long)(b * 2 + h) * 4;
            st[0] = -1e30f; st[1] = 0.f;
        }
        return;
    }
    const int nh = min(64, nact - base);

    if (tid < 64) {
        const int a = base + tid;
        act_s[tid] = g_act[b * LL + ((a < nact) ? a : base)];
    }
    qb_s[tid] = g_qb[(long)b * 256 + tid];
    w_s[tid]  = w_align[tid];
    __syncthreads();   // act_s / qb / w ready

    // stage only the nh active rows as bf16 hi/lo (rows >= nh unused)
    const float* Amol = atom + (long)b * LL * DD;
    for (int idx = tid; idx < nh * (DD / 2); idx += 256) {
        const int r  = idx >> 7;
        const int kp = idx & 127;
        const float2 v = ((const float2*)(Amol + (long)act_s[r] * DD))[kp];
        __nv_bfloat16 hx = __float2bfloat16(v.x);
        __nv_bfloat16 hy = __float2bfloat16(v.y);
        __nv_bfloat16 lx = __float2bfloat16(v.x - __bfloat162float(hx));
        __nv_bfloat16 ly = __float2bfloat16(v.y - __bfloat162float(hy));
        const int off = (r * ASTR + kp * 2) * 2;
        __nv_bfloat162 hv; hv.x = hx; hv.y = hy;
        __nv_bfloat162 lv; lv.x = lx; lv.y = ly;
        *(__nv_bfloat162*)(smem + A_HI + off) = hv;
        *(__nv_bfloat162*)(smem + A_LO + off) = lv;
    }

    uint32_t addrAh[2], addrAl[2];
    {
        const uint32_t aColh = (lane >> 4) << 3;
        #pragma unroll
        for (int mt = 0; mt < 2; ++mt) {
            const uint32_t off = (((uint32_t)(32 * mq + 16 * mt) + (lane & 15)) * ASTR + aColh) * 2;
            addrAh[mt] = smb + A_HI + off;
            addrAl[mt] = smb + A_LO + off;
        }
    }
    const char* bB0 = (const char*)g_Wf + ((uint32_t)(nq * 2 + 0)) * 512 + (uint32_t)lane * 16;
    const char* bB1 = (const char*)g_Wf + ((uint32_t)(nq * 2 + 1)) * 512 + (uint32_t)lane * 16;

    __syncthreads();   // A staged

    // warps whose 32-row strip lies entirely beyond nh skip all MMA work
    if (32 * mq < nh) {
        float sc[2][2] = {{0.f, 0.f}, {0.f, 0.f}};

        #pragma unroll 1
        for (int np = 0; np < 2; ++np) {
            float acc[2][4][4];
            #pragma unroll
            for (int mt = 0; mt < 2; ++mt)
                #pragma unroll
                for (int j = 0; j < 4; ++j)
                    #pragma unroll
                    for (int q = 0; q < 4; ++q) acc[mt][j][q] = 0.f;

            const char* b0 = bB0 + np * 4096;
            const char* b1 = bB1 + np * 4096;

            uint4 cBh0 = *(const uint4*)(b0);
            uint4 cBh1 = *(const uint4*)(b1);
            uint4 cBl0 = *(const uint4*)(b0 + 131072);
            uint4 cBl1 = *(const uint4*)(b1 + 131072);

            #pragma unroll
            for (int ks = 0; ks < 16; ++ks) {
                uint4 nBh0, nBh1, nBl0, nBl1;
                if (ks < 15) {
                    const int o = (ks + 1) * 8192;
                    nBh0 = *(const uint4*)(b0 + o);
                    nBh1 = *(const uint4*)(b1 + o);
                    nBl0 = *(const uint4*)(b0 + 131072 + o);
                    nBl1 = *(const uint4*)(b1 + 131072 + o);
                }
                uint32_t fAh[2][4], fAl[2][4];
                const uint32_t koA = (uint32_t)ks * 32;
                LDSM_X4(fAh[0][0], fAh[0][1], fAh[0][2], fAh[0][3], addrAh[0] + koA);
                LDSM_X4(fAh[1][0], fAh[1][1], fAh[1][2], fAh[1][3], addrAh[1] + koA);
                LDSM_X4(fAl[0][0], fAl[0][1], fAl[0][2], fAl[0][3], addrAl[0] + koA);
                LDSM_X4(fAl[1][0], fAl[1][1], fAl[1][2], fAl[1][3], addrAl[1] + koA);

                #pragma unroll
                for (int mt = 0; mt < 2; ++mt) {
                    float* A0 = acc[mt][0];
                    float* A1 = acc[mt][1];
                    float* A2 = acc[mt][2];
                    float* A3 = acc[mt][3];
                    MMA_BF16(A0, fAh[mt], cBh0.x, cBh0.y);
                    MMA_BF16(A0, fAl[mt], cBh0.x, cBh0.y);
                    MMA_BF16(A0, fAh[mt], cBl0.x, cBl0.y);
                    MMA_BF16(A1, fAh[mt], cBh0.z, cBh0.w);
                    MMA_BF16(A1, fAl[mt], cBh0.z, cBh0.w);
                    MMA_BF16(A1, fAh[mt], cBl0.z, cBl0.w);
                    MMA_BF16(A2, fAh[mt], cBh1.x, cBh1.y);
                    MMA_BF16(A2, fAl[mt], cBh1.x, cBh1.y);
                    MMA_BF16(A2, fAh[mt], cBl1.x, cBl1.y);
                    MMA_BF16(A3, fAh[mt], cBh1.z, cBh1.w);
                    MMA_BF16(A3, fAl[mt], cBh1.z, cBh1.w);
                    MMA_BF16(A3, fAh[mt], cBl1.z, cBl1.w);
                }
                cBh0 = nBh0; cBh1 = nBh1; cBl0 = nBl0; cBl1 = nBl1;
            }

            #pragma unroll
            for (int mt = 0; mt < 2; ++mt)
                #pragma unroll
                for (int j = 0; j < 4; ++j) {
                    const int c = np * 128 + nq * 32 + (j >> 1) * 16 + (j & 1) * 8 + (lane & 3) * 2;
                    const float q0 = qb_s[c], q1 = qb_s[c + 1];
                    const float w0 = w_s[c],  w1 = w_s[c + 1];
                    float v;
                    v = q0 + acc[mt][j][0]; v = (v >= 0.f) ? v : NEG_SLOPE * v; sc[mt][0] += v * w0;
                    v = q1 + acc[mt][j][1]; v = (v >= 0.f) ? v : NEG_SLOPE * v; sc[mt][0] += v * w1;
                    v = q0 + acc[mt][j][2]; v = (v >= 0.f) ? v : NEG_SLOPE * v; sc[mt][1] += v * w0;
                    v = q1 + acc[mt][j][3]; v = (v >= 0.f) ? v : NEG_SLOPE * v; sc[mt][1] += v * w1;
                }
        }

        #pragma unroll
        for (int mt = 0; mt < 2; ++mt)
            #pragma unroll
            for (int rh = 0; rh < 2; ++rh) {
                float t = sc[mt][rh];
                t += __shfl_xor_sync(0xffffffffu, t, 1);
                t += __shfl_xor_sync(0xffffffffu, t, 2);
                if ((lane & 3) == 0)
                    s_part[nq * 64 + 32 * mq + 16 * mt + (lane >> 2) + 8 * rh] = t;
            }
    }
    __syncthreads();

    // half-softmax stats over nh active atoms (attend=1, smask=0 for active)
    const float bal = b_align[0];
    {
        float v = (tid < nh)
                ? (bal + (s_part[tid] + s_part[64 + tid])
                       + (s_part[128 + tid] + s_part[192 + tid]))
                : -INFINITY;
        float t = v;
        #pragma unroll
        for (int off = 16; off; off >>= 1)
            t = fmaxf(t, __shfl_xor_sync(0xffffffffu, t, off));
        if (lane == 0) red[wid] = t;
        __syncthreads();
        float mx = red[0];
        #pragma unroll
        for (int w = 1; w < 8; ++w) mx = fmaxf(mx, red[w]);
        __syncthreads();

        float e = (tid < nh) ? __expf(v - mx) : 0.f;
        if (tid < 64) p_arr[tid] = e;   // attn weight (attend=1 for active)

        float ts = e;
        #pragma unroll
        for (int off = 16; off; off >>= 1)
            ts += __shfl_xor_sync(0xffffffffu, ts, off);
        if (lane == 0) red[8 + wid] = ts;
        __syncthreads();
        if (tid == 0) {
            float Z = 0.f;
            for (int w = 0; w < 8; ++w) Z += red[8 + w];
            float* st = g_st + (long)(b * 2 + h) * 4;
            st[0] = mx; st[1] = Z;
        }
    }
    __syncthreads();

    // y_half[k] = sum_a p[a] * atom[act[a],k]
    {
        float acc0 = 0.f, acc1 = 0.f;
        #pragma unroll 2
        for (int a = 0; a < 64; a += 2) {
            const float p0 = p_arr[a], p1 = p_arr[a + 1];
            if (p0 != 0.f) acc0 += p0 * Amol[(long)act_s[a] * DD + tid];
            if (p1 != 0.f) acc1 += p1 * Amol[(long)act_s[a + 1] * DD + tid];
        }
        g_y[((long)(b * 2 + h)) * 256 + tid] = acc0 + acc1;
    }
}

// K2: flash-combine + ctx GEMV (coalesced W2T) + LayerNorm. 8 mol/CTA.
__global__ __launch_bounds__(256)
void k2_tail(const float* __restrict__ b2,
             const float* __restrict__ gamma_, const float* __restrict__ beta_,
             float* __restrict__ out)
{
    __shared__ __align__(16) float y_il[256 * 8];   // [k][m]
    __shared__ __align__(16) float ctx_s[8 * 256];
    __shared__ float cs[8][4];
    const int bm0 = blockIdx.x * 8;
    const int tid = threadIdx.x;
    const int lane = tid & 31;
    const int wid = tid >> 5;

    if (tid < 8) {
        const float* st = g_st + (long)(bm0 + tid) * 8;
        const float m0 = st[0], Z0 = st[1];
        const float m1 = st[4], Z1 = st[5];
        const float mx = fmaxf(m0, m1);
        const float s0 = __expf(m0 - mx), s1 = __expf(m1 - mx);
        const float Z = Z0 * s0 + Z1 * s1;
        const float inv = (Z > 0.f) ? (1.f / Z) : 0.f;
        cs[tid][0] = s0 * inv;
        cs[tid][1] = s1 * inv;
        cs[tid][2] = (Z > 0.f) ? 1.f : 0.f;   // sum of attn over actives
    }
    __syncthreads();
    for (int i = tid; i < 8 * 256; i += 256) {
        const int k = i >> 3, m = i & 7;
        y_il[i] = g_y[(long)(bm0 + m) * 2 * 256 + k] * cs[m][0]
                + g_y[((long)(bm0 + m) * 2 + 1) * 256 + k] * cs[m][1];
    }
    __syncthreads();
    {
        const int d = tid;
        const float b2d = b2[d];
        float acc[8];
        #pragma unroll
        for (int m = 0; m < 8; ++m) acc[m] = cs[m][2] * b2d;
        #pragma unroll 4
        for (int k = 0; k < 256; ++k) {
            const float wv = g_W2T[(long)k * 256 + d];   // coalesced
            const float4 y0 = *(const float4*)(y_il + k * 8);
            const float4 y1 = *(const float4*)(y_il + k * 8 + 4);
            acc[0] += y0.x * wv; acc[1] += y0.y * wv;
            acc[2] += y0.z * wv; acc[3] += y0.w * wv;
            acc[4] += y1.x * wv; acc[5] += y1.y * wv;
            acc[6] += y1.z * wv; acc[7] += y1.w * wv;
        }
        #pragma unroll
        for (int m = 0; m < 8; ++m) ctx_s[m * 256 + d] = acc[m];
    }
    __syncthreads();
    {   // LN: warp w -> molecule w
        const int m = wid;
        float vals[8];
        float s1 = 0.f;
        #pragma unroll
        for (int j = 0; j < 8; ++j) {
            vals[j] = ctx_s[m * 256 + lane + 32 * j];
            s1 += vals[j];
        }
        #pragma unroll
        for (int off = 16; off; off >>= 1)
            s1 += __shfl_xor_sync(0xffffffffu, s1, off);
        const float mu = s1 * (1.f / 256.f);
        float s2 = 0.f;
        #pragma unroll
        for (int j = 0; j < 8; ++j) {
            const float d = vals[j] - mu;
            s2 += d * d;
        }
        #pragma unroll
        for (int off = 16; off; off >>= 1)
            s2 += __shfl_xor_sync(0xffffffffu, s2, off);
        const float inv = rsqrtf(s2 * (1.f / 256.f) + LN_EPS);
        #pragma unroll
        for (int j = 0; j < 8; ++j) {
            const int d = lane + 32 * j;
            out[(long)(bm0 + m) * 256 + d] =
                (vals[j] - mu) * inv * gamma_[d] + beta_[d];
        }
    }
}

extern "C" void kernel_launch(void* const* d_in, const int* in_sizes, int n_in,
                              void* d_out, int out_size)
{
    const float* mol     = (const float*)d_in[0];
    const float* atom    = (const float*)d_in[1];
    const float* attend  = (const float*)d_in[2];
    const float* W1      = (const float*)d_in[4];
    const float* b1      = (const float*)d_in[5];
    const float* W2      = (const float*)d_in[6];
    const float* b2      = (const float*)d_in[7];
    const float* w_align = (const float*)d_in[8];
    const float* b_align = (const float*)d_in[9];
    const float* gamma_  = (const float*)d_in[10];
    const float* beta_   = (const float*)d_in[11];
    float* out = (float*)d_out;

    const int B = in_sizes[0] / DD;

    prep_wf<<<64, 256>>>(W2);
    prep_wt<<<256, 256>>>(W1, W2);
    prep_act<<<B, 128>>>(attend);
    prep_qb<<<B / 8, 256>>>(mol, b1, b2);

    cudaFuncSetAttribute(k1_scores,
                         cudaFuncAttributeMaxDynamicSharedMemorySize, K1_SMEM);
    k1_scores<<<B * 2, 256, K1_SMEM>>>(atom, w_align, b_align);

    k2_tail<<<B / 8, 256>>>(b2, gamma_, beta_, out);
}